// round 9
// baseline (speedup 1.0000x reference)
#include <cuda_runtime.h>
#include <cuda_bf16.h>
#include <float.h>

// Segmented 3-NN cosine-consistency loss, LDG-broadcast full-scan edition.
//
// Kernel 1 (pack): g_pack[i] = (-2x,-2y,-2z,|c|^2) for each point.
// Kernel 2 (knn_loss): one thread = one row; grid of 1-warp blocks (1024
//   blocks -> near-perfect wave balance on 148 SMs). Each thread scans its
//   ENTIRE segment with a carried top-3 threshold (inserts ~3*ln(S) total
//   -> ~17% warp-any divergence), reading candidates via broadcast LDG.128
//   from the packed L2/L1-resident array. Hot path: LDG.128 + 3 FFMA +
//   FSETP, unroll 8. Top-3 tracked in e-space (e = |cj|^2 - 2 ci.cj;
//   ordering identical to clamped d2; ascending-j scan + strict < matches
//   jax.lax.top_k's lower-index tie-break). Inline cosine-loss epilogue;
//   warp-reduced partial per block.
// Kernel 3 (finalize): deterministic reduction of block partials.

#define TPACK 256
#define T1    32
#define TFIN  256

__device__ float4 g_pack[32768];
__device__ float  g_partials[4096];

__device__ __forceinline__ float dot3(float ax, float ay, float az,
                                      float bx, float by, float bz) {
    return fmaf(ax, bx, fmaf(ay, by, az * bz));
}

// strict-< sorted insert of (e, j) into (E0<=E1<=E2); with ascending-j
// arrival this reproduces top_k's lower-index tie-break.
__device__ __forceinline__ void ins3e(float e, int j,
                                      float& E0, int& J0,
                                      float& E1, int& J1,
                                      float& E2, int& J2) {
    if (e < E1) {
        E2 = E1; J2 = J1;
        if (e < E0) { E1 = E0; J1 = J0; E0 = e; J0 = j; }
        else        { E1 = e;  J1 = j; }
    } else { E2 = e; J2 = j; }
}

__global__ void __launch_bounds__(TPACK)
pack_kernel(const float* __restrict__ coord, int npts) {
    const int i = blockIdx.x * TPACK + threadIdx.x;
    if (i < npts) {
        const float x = coord[3 * i + 0];
        const float y = coord[3 * i + 1];
        const float z = coord[3 * i + 2];
        g_pack[i] = make_float4(-2.f * x, -2.f * y, -2.f * z,
                                x * x + y * y + z * z);
    }
}

__global__ void __launch_bounds__(T1)
knn_loss_kernel(const float* __restrict__ pred,
                const float* __restrict__ target,
                int seg, int npts) {
    const int r = blockIdx.x * T1 + threadIdx.x;   // global row
    float acc = 0.0f;

    if (r < npts) {
        const int  segIdx = r / seg;
        const int  base   = segIdx * seg;
        const int  i      = r - base;              // local row
        const float4 ci   = g_pack[r];
        const float xi = -0.5f * ci.x;
        const float yi = -0.5f * ci.y;
        const float zi = -0.5f * ci.z;

        float E0 = FLT_MAX, E1 = FLT_MAX, E2 = FLT_MAX;
        int   J0 = -1, J1 = -1, J2 = -1;

        const float4* __restrict__ cp = &g_pack[base];
        #pragma unroll 8
        for (int t = 0; t < seg; t++) {
            const float4 c = cp[t];
            const float e = fmaf(c.x, xi, fmaf(c.y, yi, fmaf(c.z, zi, c.w)));
            if (e < E2) {                      // rare after warm-up (~25/seg)
                if (t != i) ins3e(e, t, E0, J0, E1, J1, E2, J2);
            }
        }

        // ---- epilogue: neighbor similarity loss ----
        const long gi = r;
        float px = pred[3 * gi + 0], py = pred[3 * gi + 1], pz = pred[3 * gi + 2];
        float inpv = sqrtf(px * px + py * py + pz * pz + 1e-8f) + 1e-10f;
        float pnx = px / inpv, pny = py / inpv, pnz = pz / inpv;

        float tx = target[3 * gi + 0], ty = target[3 * gi + 1], tz = target[3 * gi + 2];

        const int nbr[3] = { J0, J1, J2 };
        #pragma unroll
        for (int k = 0; k < 3; k++) {
            const long gj = (long)base + nbr[k];
            float qx = pred[3 * gj + 0], qy = pred[3 * gj + 1], qz = pred[3 * gj + 2];
            float inq = sqrtf(qx * qx + qy * qy + qz * qz + 1e-8f) + 1e-10f;
            float sim = fminf(fabsf(dot3(qx / inq, qy / inq, qz / inq,
                                         pnx, pny, pnz)), 1.0f);

            float ux = target[3 * gj + 0], uy = target[3 * gj + 1], uz = target[3 * gj + 2];
            float tsim = fminf(fabsf(dot3(ux, uy, uz, tx, ty, tz)), 1.0f);

            float diff = sim - tsim;
            acc = fmaf(diff, diff, acc);
        }
    }

    // ---- warp reduction (block = 1 warp) ----
    #pragma unroll
    for (int off = 16; off > 0; off >>= 1)
        acc += __shfl_down_sync(0xffffffffu, acc, off);
    if (threadIdx.x == 0) g_partials[blockIdx.x] = acc;
}

__global__ void __launch_bounds__(TFIN)
finalize_kernel(float* __restrict__ out, int nblocks, float invCount) {
    __shared__ float red[TFIN];
    float s = 0.0f;
    for (int b = threadIdx.x; b < nblocks; b += TFIN) s += g_partials[b];
    red[threadIdx.x] = s;
    __syncthreads();
    #pragma unroll
    for (int st = TFIN / 2; st > 0; st >>= 1) {
        if (threadIdx.x < st) red[threadIdx.x] += red[threadIdx.x + st];
        __syncthreads();
    }
    if (threadIdx.x == 0) out[0] = red[0] * invCount;
}

extern "C" void kernel_launch(void* const* d_in, const int* in_sizes, int n_in,
                              void* d_out, int out_size) {
    const float* pred   = (const float*)d_in[0];
    const float* coord  = (const float*)d_in[1];
    const float* target = (const float*)d_in[2];
    const int    nseg   = in_sizes[3];           // nums has nseg elements
    const int    npts   = in_sizes[0] / 3;
    const int    seg    = npts / nseg;

    const int gridPack = (npts + TPACK - 1) / TPACK;
    pack_kernel<<<gridPack, TPACK>>>(coord, npts);

    const int gridKnn = (npts + T1 - 1) / T1;    // 1024 one-warp blocks
    knn_loss_kernel<<<gridKnn, T1>>>(pred, target, seg, npts);

    const float invCount = 1.0f / ((float)npts * 3.0f);
    finalize_kernel<<<1, TFIN>>>((float*)d_out, gridKnn, invCount);
}

// round 10
// speedup vs baseline: 2.1496x; 2.1496x over previous
#include <cuda_runtime.h>
#include <cuda_bf16.h>
#include <float.h>

// Segmented 3-NN cosine-consistency loss, tuned column-block edition.
//
// Kernel 1 (knn_partial): grid = nseg * rowTiles * NCB(=2) blocks of 128
//   threads. Each block: 128 rows x one 2048-point column strip staged in
//   smem as (-2x,-2y,-2z,|c|^2) (32 KB). One thread = one row: all lanes
//   broadcast-read the same smem entry (conflict-free). Long strips keep the
//   per-thread insert rate at ~1.3%/iter -> warp-any divergence ~33%.
//   Top-3 in e-space; sorted (e, j) triples per (row, strip) to scratch.
// Kernel 2 (merge_epilogue): per row, merge the 2 partial lists in ascending
//   strip order (strict < == top_k lower-index tie-break), then the
//   neighbor-cosine loss term; block reduction.
// Kernel 3 (finalize): deterministic reduction of block partials.

#define T1    128      // threads (= rows) per knn block
#define NCB   2        // column strips per segment
#define T2    256
#define TFIN  256

__device__ float g_pe[32768 * NCB * 3];
__device__ int   g_pj[32768 * NCB * 3];
__device__ float g_partials[256];

__device__ __forceinline__ float dot3(float ax, float ay, float az,
                                      float bx, float by, float bz) {
    return fmaf(ax, bx, fmaf(ay, by, az * bz));
}

// strict-< sorted insert of (e, j) into (E0<=E1<=E2); ascending-j arrival
// order makes this exactly top_k's lower-index tie-break.
__device__ __forceinline__ void ins3e(float e, int j,
                                      float& E0, int& J0,
                                      float& E1, int& J1,
                                      float& E2, int& J2) {
    if (e < E1) {
        E2 = E1; J2 = J1;
        if (e < E0) { E1 = E0; J1 = J0; E0 = e; J0 = j; }
        else        { E1 = e;  J1 = j; }
    } else { E2 = e; J2 = j; }
}

__global__ void __launch_bounds__(T1)
knn_partial(const float* __restrict__ coord,
            int seg, int rowTiles, int colT) {
    extern __shared__ float4 s_c[];   // colT entries

    const int cb      = blockIdx.x % NCB;
    const int tmp     = blockIdx.x / NCB;
    const int rowTile = tmp % rowTiles;
    const int segIdx  = tmp / rowTiles;
    const int i       = rowTile * T1 + threadIdx.x;   // local row
    const long segOff = (long)segIdx * seg;

    const int cBeg = cb * colT;
    const int tlen = min(seg - cBeg, colT);

    // stage column strip
    for (int t = threadIdx.x; t < tlen; t += T1) {
        const long gj = segOff + cBeg + t;
        float x = coord[3 * gj + 0];
        float y = coord[3 * gj + 1];
        float z = coord[3 * gj + 2];
        s_c[t] = make_float4(-2.f * x, -2.f * y, -2.f * z,
                             x * x + y * y + z * z);
    }
    __syncthreads();

    if (i < seg) {
        const long gi = segOff + i;
        const float xi = coord[3 * gi + 0];
        const float yi = coord[3 * gi + 1];
        const float zi = coord[3 * gi + 2];

        float E0 = FLT_MAX, E1 = FLT_MAX, E2 = FLT_MAX;
        int   J0 = -1, J1 = -1, J2 = -1;

        #pragma unroll 8
        for (int t = 0; t < tlen; t++) {
            const float4 c = s_c[t];
            const float e = fmaf(c.x, xi, fmaf(c.y, yi, fmaf(c.z, zi, c.w)));
            if (e < E2) {                  // ~1.3% of iters per thread
                const int j = cBeg + t;
                if (j != i) ins3e(e, j, E0, J0, E1, J1, E2, J2);
            }
        }

        const long base = ((segOff + i) * NCB + cb) * 3;
        g_pe[base + 0] = E0; g_pj[base + 0] = J0;
        g_pe[base + 1] = E1; g_pj[base + 1] = J1;
        g_pe[base + 2] = E2; g_pj[base + 2] = J2;
    }
}

__global__ void __launch_bounds__(T2)
merge_epilogue(const float* __restrict__ pred,
               const float* __restrict__ target,
               int seg, int nrows) {
    const int r = blockIdx.x * T2 + threadIdx.x;   // global row
    float acc = 0.0f;

    if (r < nrows) {
        float E0 = FLT_MAX, E1 = FLT_MAX, E2 = FLT_MAX;
        int   J0 = -1, J1 = -1, J2 = -1;

        #pragma unroll
        for (int cb = 0; cb < NCB; cb++) {
            const long base = ((long)r * NCB + cb) * 3;
            #pragma unroll
            for (int k = 0; k < 3; k++) {
                const float e = g_pe[base + k];
                if (e < E2) {
                    const int j = g_pj[base + k];
                    ins3e(e, j, E0, J0, E1, J1, E2, J2);
                }
            }
        }

        const int  segIdx = r / seg;
        const long segOff = (long)segIdx * seg;
        const long gi     = r;

        float px = pred[3 * gi + 0], py = pred[3 * gi + 1], pz = pred[3 * gi + 2];
        float inpv = sqrtf(px * px + py * py + pz * pz + 1e-8f) + 1e-10f;
        float pnx = px / inpv, pny = py / inpv, pnz = pz / inpv;

        float tx = target[3 * gi + 0], ty = target[3 * gi + 1], tz = target[3 * gi + 2];

        const int nbr[3] = { J0, J1, J2 };
        #pragma unroll
        for (int k = 0; k < 3; k++) {
            const long gj = segOff + nbr[k];
            float qx = pred[3 * gj + 0], qy = pred[3 * gj + 1], qz = pred[3 * gj + 2];
            float inq = sqrtf(qx * qx + qy * qy + qz * qz + 1e-8f) + 1e-10f;
            float sim = fminf(fabsf(dot3(qx / inq, qy / inq, qz / inq,
                                         pnx, pny, pnz)), 1.0f);

            float ux = target[3 * gj + 0], uy = target[3 * gj + 1], uz = target[3 * gj + 2];
            float tsim = fminf(fabsf(dot3(ux, uy, uz, tx, ty, tz)), 1.0f);

            float diff = sim - tsim;
            acc = fmaf(diff, diff, acc);
        }
    }

    __shared__ float red[T2];
    red[threadIdx.x] = acc;
    __syncthreads();
    #pragma unroll
    for (int s = T2 / 2; s > 0; s >>= 1) {
        if (threadIdx.x < s) red[threadIdx.x] += red[threadIdx.x + s];
        __syncthreads();
    }
    if (threadIdx.x == 0) g_partials[blockIdx.x] = red[0];
}

__global__ void __launch_bounds__(TFIN)
finalize_kernel(float* __restrict__ out, int nblocks, float invCount) {
    __shared__ float red[TFIN];
    float s = 0.0f;
    for (int b = threadIdx.x; b < nblocks; b += TFIN) s += g_partials[b];
    red[threadIdx.x] = s;
    __syncthreads();
    #pragma unroll
    for (int st = TFIN / 2; st > 0; st >>= 1) {
        if (threadIdx.x < st) red[threadIdx.x] += red[threadIdx.x + st];
        __syncthreads();
    }
    if (threadIdx.x == 0) out[0] = red[0] * invCount;
}

extern "C" void kernel_launch(void* const* d_in, const int* in_sizes, int n_in,
                              void* d_out, int out_size) {
    const float* pred   = (const float*)d_in[0];
    const float* coord  = (const float*)d_in[1];
    const float* target = (const float*)d_in[2];
    const int    nseg   = in_sizes[3];           // nums has nseg elements
    const int    npts   = in_sizes[0] / 3;
    const int    seg    = npts / nseg;

    const int colT     = (seg + NCB - 1) / NCB;  // 2048 at seg=4096
    const int rowTiles = (seg + T1 - 1) / T1;    // 32
    const int grid1    = nseg * rowTiles * NCB;  // 512
    const size_t smem1 = (size_t)colT * sizeof(float4);  // 32 KB

    static bool attrDone = false;
    if (!attrDone) {
        cudaFuncSetAttribute(knn_partial,
                             cudaFuncAttributeMaxDynamicSharedMemorySize,
                             (int)smem1);
        attrDone = true;
    }

    knn_partial<<<grid1, T1, smem1>>>(coord, seg, rowTiles, colT);

    const int nrows = nseg * seg;
    const int grid2 = (nrows + T2 - 1) / T2;
    merge_epilogue<<<grid2, T2>>>(pred, target, seg, nrows);

    const float invCount = 1.0f / ((float)nrows * 3.0f);
    finalize_kernel<<<1, TFIN>>>((float*)d_out, grid2, invCount);
}

// round 12
// speedup vs baseline: 2.7586x; 1.2833x over previous
#include <cuda_runtime.h>
#include <cuda_bf16.h>
#include <float.h>
#include <limits.h>

// Segmented exact 3-NN cosine-consistency loss via per-segment spatial
// binning (G^3 grid, ~8 pts/cell). Exactness: candidates compared with
// lexicographic (clamped d2, original j) -- visit-order independent and
// identical to jax.lax.top_k's lower-index tie-break; ring search expands
// until 3rd-best d2 <= squared distance to searched-box boundary (domain-
// edge faces = infinity). KNN scans in binned order (spatially coherent
// warps); results land at original ids, so the loss epilogue + reduction
// run in fixed original order -> deterministic output.

#define G       8
#define NC      (G * G * G)         // 512 cells per segment
#define MAXPTS  32768
#define MAXCELL 16384
#define TB      256
#define TK      128

__device__ unsigned g_bbox[6];      // encoded min xyz, max xyz
__device__ int      g_binCnt[MAXCELL];
__device__ int      g_binOff[MAXCELL];
__device__ int      g_binFill[MAXCELL];
__device__ int      g_cellOf[MAXPTS];
__device__ int      g_sortedIdx[MAXPTS];
__device__ float4   g_packed[MAXPTS];   // binned order: (-2x,-2y,-2z,|c|^2)
__device__ int      g_nbr[MAXPTS * 3];  // by original id
__device__ float    g_partials[256];

__device__ __forceinline__ unsigned encf(float f) {
    unsigned u = __float_as_uint(f);
    return (u & 0x80000000u) ? ~u : (u | 0x80000000u);
}
__device__ __forceinline__ float decf(unsigned u) {
    u = (u & 0x80000000u) ? (u ^ 0x80000000u) : ~u;
    return __uint_as_float(u);
}

__device__ __forceinline__ float dot3(float ax, float ay, float az,
                                      float bx, float by, float bz) {
    return fmaf(ax, bx, fmaf(ay, by, az * bz));
}

__device__ __forceinline__ bool lessDJ(float da, int ja, float db, int jb) {
    return (da < db) || (da == db && ja < jb);
}

// load bbox -> lo[3], cellW[3], scale[3] (identical arithmetic everywhere)
__device__ __forceinline__ void loadGridParams(float* lo, float* cw, float* sc) {
    #pragma unroll
    for (int a = 0; a < 3; a++) {
        const float l = decf(g_bbox[a]);
        const float h = decf(g_bbox[3 + a]);
        const float span = fmaxf(h - l, 1e-20f);
        lo[a] = l;
        cw[a] = span / (float)G;
        sc[a] = (float)G * (1.0f - 1e-6f) / span;
    }
}

__device__ __forceinline__ int cellIdx(float v, float lo, float sc) {
    int c = (int)((v - lo) * sc);
    return min(G - 1, max(0, c));
}

// ---------------- pipeline kernels ----------------

__global__ void __launch_bounds__(TB)
init_kernel(int ncells) {
    const int i = blockIdx.x * TB + threadIdx.x;
    if (i < ncells) g_binCnt[i] = 0;
    if (i < 3) { g_bbox[i] = 0xFFFFFFFFu; g_bbox[3 + i] = 0u; }
}

__global__ void __launch_bounds__(TB)
bbox_kernel(const float* __restrict__ coord, int npts) {
    __shared__ unsigned sh[TB];
    unsigned mn[3] = {0xFFFFFFFFu, 0xFFFFFFFFu, 0xFFFFFFFFu};
    unsigned mx[3] = {0u, 0u, 0u};
    for (int i = blockIdx.x * TB + threadIdx.x; i < npts;
         i += gridDim.x * TB) {
        #pragma unroll
        for (int a = 0; a < 3; a++) {
            const unsigned e = encf(coord[3 * i + a]);
            mn[a] = min(mn[a], e);
            mx[a] = max(mx[a], e);
        }
    }
    #pragma unroll
    for (int a = 0; a < 3; a++) {
        sh[threadIdx.x] = mn[a]; __syncthreads();
        for (int s = TB / 2; s > 0; s >>= 1) {
            if (threadIdx.x < s) sh[threadIdx.x] = min(sh[threadIdx.x], sh[threadIdx.x + s]);
            __syncthreads();
        }
        if (threadIdx.x == 0) atomicMin(&g_bbox[a], sh[0]);
        __syncthreads();
        sh[threadIdx.x] = mx[a]; __syncthreads();
        for (int s = TB / 2; s > 0; s >>= 1) {
            if (threadIdx.x < s) sh[threadIdx.x] = max(sh[threadIdx.x], sh[threadIdx.x + s]);
            __syncthreads();
        }
        if (threadIdx.x == 0) atomicMax(&g_bbox[3 + a], sh[0]);
        __syncthreads();
    }
}

__global__ void __launch_bounds__(TB)
count_kernel(const float* __restrict__ coord, int npts, int seg) {
    const int i = blockIdx.x * TB + threadIdx.x;
    if (i >= npts) return;
    float lo[3], cw[3], sc[3];
    loadGridParams(lo, cw, sc);
    const float x = coord[3 * i + 0];
    const float y = coord[3 * i + 1];
    const float z = coord[3 * i + 2];
    const int cx = cellIdx(x, lo[0], sc[0]);
    const int cy = cellIdx(y, lo[1], sc[1]);
    const int cz = cellIdx(z, lo[2], sc[2]);
    const int cell = (i / seg) * NC + (cz * G + cy) * G + cx;
    g_cellOf[i] = cell;
    atomicAdd(&g_binCnt[cell], 1);
}

__global__ void __launch_bounds__(1024)
scan_kernel(int ncells) {
    __shared__ int tsum[1024];
    const int tid = threadIdx.x;
    const int per = (ncells + 1023) / 1024;
    int local[16];                       // per <= 16 for MAXCELL=16384
    int s = 0;
    for (int q = 0; q < per; q++) {
        const int idx = tid * per + q;
        local[q] = s;
        if (idx < ncells) s += g_binCnt[idx];
    }
    tsum[tid] = s;
    __syncthreads();
    for (int off = 1; off < 1024; off <<= 1) {
        int v = (tid >= off) ? tsum[tid - off] : 0;
        __syncthreads();
        tsum[tid] += v;
        __syncthreads();
    }
    const int prefix = (tid > 0) ? tsum[tid - 1] : 0;
    for (int q = 0; q < per; q++) {
        const int idx = tid * per + q;
        if (idx < ncells) {
            const int o = prefix + local[q];
            g_binOff[idx]  = o;
            g_binFill[idx] = o;
        }
    }
}

__global__ void __launch_bounds__(TB)
scatter_kernel(const float* __restrict__ coord, int npts) {
    const int i = blockIdx.x * TB + threadIdx.x;
    if (i >= npts) return;
    const int pos = atomicAdd(&g_binFill[g_cellOf[i]], 1);
    const float x = coord[3 * i + 0];
    const float y = coord[3 * i + 1];
    const float z = coord[3 * i + 2];
    g_sortedIdx[pos] = i;
    g_packed[pos] = make_float4(-2.f * x, -2.f * y, -2.f * z,
                                x * x + y * y + z * z);
}

__global__ void __launch_bounds__(TK)
knn_kernel(int npts, int seg) {
    const int k = blockIdx.x * TK + threadIdx.x;
    if (k >= npts) return;

    float lo[3], cw[3], sc[3];
    loadGridParams(lo, cw, sc);

    const float4 pk = g_packed[k];
    const float px = -0.5f * pk.x;
    const float py = -0.5f * pk.y;
    const float pz = -0.5f * pk.z;
    const float sqi = pk.w;
    const int   i   = g_sortedIdx[k];
    const int   cellBase = (i / seg) * NC;

    const int cx = cellIdx(px, lo[0], sc[0]);
    const int cy = cellIdx(py, lo[1], sc[1]);
    const int cz = cellIdx(pz, lo[2], sc[2]);

    float D0 = FLT_MAX, D1 = FLT_MAX, D2 = FLT_MAX;
    int   J0 = -1, J1 = -1, J2 = -1;

    for (int R = 1; R <= G; R++) {
        const int zlo = max(cz - R, 0), zhi = min(cz + R, G - 1);
        const int ylo = max(cy - R, 0), yhi = min(cy + R, G - 1);
        const int xlo = max(cx - R, 0), xhi = min(cx + R, G - 1);
        for (int zc = zlo; zc <= zhi; zc++) {
            const int adz = abs(zc - cz);
            for (int yc = ylo; yc <= yhi; yc++) {
                const int ady = abs(yc - cy);
                for (int xc = xlo; xc <= xhi; xc++) {
                    if (R > 1) {
                        const int adx = abs(xc - cx);
                        if (max(adx, max(ady, adz)) < R) continue;  // already searched
                    }
                    const int cell = cellBase + (zc * G + yc) * G + xc;
                    const int off  = g_binOff[cell];
                    const int end  = off + g_binCnt[cell];
                    for (int t = off; t < end; t++) {
                        const float4 c = g_packed[t];
                        const float e = fmaf(c.x, px, fmaf(c.y, py, fmaf(c.z, pz, c.w)));
                        const float d2 = fmaxf(sqi + e, 0.0f);
                        if (d2 <= D2) {
                            const int j = g_sortedIdx[t];
                            if (j != i && lessDJ(d2, j, D2, J2)) {
                                if (lessDJ(d2, j, D1, J1)) {
                                    D2 = D1; J2 = J1;
                                    if (lessDJ(d2, j, D0, J0)) { D1 = D0; J1 = J0; D0 = d2; J0 = j; }
                                    else                       { D1 = d2; J1 = j; }
                                } else { D2 = d2; J2 = j; }
                            }
                        }
                    }
                }
            }
        }
        // termination: all unsearched cells lie beyond the searched box
        if (J2 >= 0) {
            float b = FLT_MAX;
            if (cx - R > 0)     b = fminf(b, px - (lo[0] + (float)(cx - R) * cw[0]));
            if (cx + R < G - 1) b = fminf(b, (lo[0] + (float)(cx + R + 1) * cw[0]) - px);
            if (cy - R > 0)     b = fminf(b, py - (lo[1] + (float)(cy - R) * cw[1]));
            if (cy + R < G - 1) b = fminf(b, (lo[1] + (float)(cy + R + 1) * cw[1]) - py);
            if (cz - R > 0)     b = fminf(b, pz - (lo[2] + (float)(cz - R) * cw[2]));
            if (cz + R < G - 1) b = fminf(b, (lo[2] + (float)(cz + R + 1) * cw[2]) - pz);
            if (b == FLT_MAX || D2 <= b * b) break;
        }
    }

    g_nbr[3 * i + 0] = J0;
    g_nbr[3 * i + 1] = J1;
    g_nbr[3 * i + 2] = J2;
}

__global__ void __launch_bounds__(TB)
epilogue_kernel(const float* __restrict__ pred,
                const float* __restrict__ target,
                int npts) {
    const int r = blockIdx.x * TB + threadIdx.x;   // original point id
    float acc = 0.0f;

    if (r < npts) {
        const long gi = r;
        float fx = pred[3 * gi + 0], fy = pred[3 * gi + 1], fz = pred[3 * gi + 2];
        float inpv = sqrtf(fx * fx + fy * fy + fz * fz + 1e-8f) + 1e-10f;
        float pnx = fx / inpv, pny = fy / inpv, pnz = fz / inpv;

        float tx = target[3 * gi + 0], ty = target[3 * gi + 1], tz = target[3 * gi + 2];

        #pragma unroll
        for (int k = 0; k < 3; k++) {
            const long gj = g_nbr[3 * r + k];      // global original index
            float qx = pred[3 * gj + 0], qy = pred[3 * gj + 1], qz = pred[3 * gj + 2];
            float inq = sqrtf(qx * qx + qy * qy + qz * qz + 1e-8f) + 1e-10f;
            float sim = fminf(fabsf(dot3(qx / inq, qy / inq, qz / inq,
                                         pnx, pny, pnz)), 1.0f);

            float ux = target[3 * gj + 0], uy = target[3 * gj + 1], uz = target[3 * gj + 2];
            float tsim = fminf(fabsf(dot3(ux, uy, uz, tx, ty, tz)), 1.0f);

            float diff = sim - tsim;
            acc = fmaf(diff, diff, acc);
        }
    }

    __shared__ float red[TB];
    red[threadIdx.x] = acc;
    __syncthreads();
    #pragma unroll
    for (int s = TB / 2; s > 0; s >>= 1) {
        if (threadIdx.x < s) red[threadIdx.x] += red[threadIdx.x + s];
        __syncthreads();
    }
    if (threadIdx.x == 0) g_partials[blockIdx.x] = red[0];
}

__global__ void __launch_bounds__(TB)
finalize_kernel(float* __restrict__ out, int nblocks, float invCount) {
    __shared__ float red[TB];
    float s = 0.0f;
    for (int b = threadIdx.x; b < nblocks; b += TB) s += g_partials[b];
    red[threadIdx.x] = s;
    __syncthreads();
    #pragma unroll
    for (int st = TB / 2; st > 0; st >>= 1) {
        if (threadIdx.x < st) red[threadIdx.x] += red[threadIdx.x + st];
        __syncthreads();
    }
    if (threadIdx.x == 0) out[0] = red[0] * invCount;
}

extern "C" void kernel_launch(void* const* d_in, const int* in_sizes, int n_in,
                              void* d_out, int out_size) {
    const float* pred   = (const float*)d_in[0];
    const float* coord  = (const float*)d_in[1];
    const float* target = (const float*)d_in[2];
    const int    nseg   = in_sizes[3];
    const int    npts   = in_sizes[0] / 3;
    const int    seg    = npts / nseg;
    const int    ncells = nseg * NC;

    const int gPts = (npts + TB - 1) / TB;

    init_kernel<<<(ncells + TB - 1) / TB, TB>>>(ncells);
    bbox_kernel<<<64, TB>>>(coord, npts);
    count_kernel<<<gPts, TB>>>(coord, npts, seg);
    scan_kernel<<<1, 1024>>>(ncells);
    scatter_kernel<<<gPts, TB>>>(coord, npts);
    knn_kernel<<<(npts + TK - 1) / TK, TK>>>(npts, seg);
    epilogue_kernel<<<gPts, TB>>>(pred, target, npts);

    const float invCount = 1.0f / ((float)npts * 3.0f);
    finalize_kernel<<<1, TB>>>((float*)d_out, gPts, invCount);
}

// round 13
// speedup vs baseline: 2.9991x; 1.0872x over previous
#include <cuda_runtime.h>
#include <cuda_bf16.h>
#include <float.h>

// Segmented exact 3-NN cosine-consistency loss via per-segment spatial
// binning. 5-launch pipeline:
//   1) bbox:        grid-stride min/max -> g_bbox (encoded atomics)
//   2) count+scan:  per-point cell + counts; LAST block (ticket) runs the
//                   4096-cell prefix scan (2-pass, shuffle-based)
//   3) scatter:     points -> binned slots (atomic within cell)
//   4) knn+loss:    ring search in binned order; lexicographic (d2, j)
//                   compare == jax.lax.top_k lower-index tie-break and is
//                   scatter-order independent; termination when 3rd-best
//                   d2 <= dist^2 to searched-box boundary (domain-edge
//                   faces = infinity). Writes per-point loss by ORIGINAL id.
//   5) reduce:      deterministic fixed-order sum of 32768 losses -> out,
//                   then resets g_bbox/g_ticket/g_binCnt for next replay
//                   (first run uses the static initializers).

#define G       8
#define NC      (G * G * G)
#define MAXPTS  32768
#define MAXCELL 16384
#define TB      256

__device__ unsigned g_bbox[6] = {0xFFFFFFFFu, 0xFFFFFFFFu, 0xFFFFFFFFu, 0u, 0u, 0u};
__device__ int      g_ticket  = 0;
__device__ int      g_binCnt[MAXCELL];          // zero-initialized
__device__ int      g_binOff[MAXCELL];
__device__ int      g_binFill[MAXCELL];
__device__ int      g_cellOf[MAXPTS];
__device__ int      g_sortedIdx[MAXPTS];
__device__ float4   g_packed[MAXPTS];           // binned: (-2x,-2y,-2z,|c|^2)
__device__ float    g_loss[MAXPTS];             // by original id

__device__ __forceinline__ unsigned encf(float f) {
    unsigned u = __float_as_uint(f);
    return (u & 0x80000000u) ? ~u : (u | 0x80000000u);
}
__device__ __forceinline__ float decf(unsigned u) {
    u = (u & 0x80000000u) ? (u ^ 0x80000000u) : ~u;
    return __uint_as_float(u);
}
__device__ __forceinline__ float dot3(float ax, float ay, float az,
                                      float bx, float by, float bz) {
    return fmaf(ax, bx, fmaf(ay, by, az * bz));
}
__device__ __forceinline__ bool lessDJ(float da, int ja, float db, int jb) {
    return (da < db) || (da == db && ja < jb);
}
__device__ __forceinline__ void loadGridParams(float* lo, float* cw, float* sc) {
    #pragma unroll
    for (int a = 0; a < 3; a++) {
        const float l = decf(g_bbox[a]);
        const float h = decf(g_bbox[3 + a]);
        const float span = fmaxf(h - l, 1e-20f);
        lo[a] = l;
        cw[a] = span / (float)G;
        sc[a] = (float)G * (1.0f - 1e-6f) / span;
    }
}
__device__ __forceinline__ int cellIdx(float v, float lo, float sc) {
    int c = (int)((v - lo) * sc);
    return min(G - 1, max(0, c));
}

// ---------------- 1: bbox ----------------
__global__ void __launch_bounds__(TB)
bbox_kernel(const float* __restrict__ coord, int npts) {
    __shared__ unsigned sh[TB];
    unsigned mn[3] = {0xFFFFFFFFu, 0xFFFFFFFFu, 0xFFFFFFFFu};
    unsigned mx[3] = {0u, 0u, 0u};
    for (int i = blockIdx.x * TB + threadIdx.x; i < npts; i += gridDim.x * TB) {
        #pragma unroll
        for (int a = 0; a < 3; a++) {
            const unsigned e = encf(coord[3 * i + a]);
            mn[a] = min(mn[a], e);
            mx[a] = max(mx[a], e);
        }
    }
    #pragma unroll
    for (int a = 0; a < 3; a++) {
        sh[threadIdx.x] = mn[a]; __syncthreads();
        for (int s = TB / 2; s > 0; s >>= 1) {
            if (threadIdx.x < s) sh[threadIdx.x] = min(sh[threadIdx.x], sh[threadIdx.x + s]);
            __syncthreads();
        }
        if (threadIdx.x == 0) atomicMin(&g_bbox[a], sh[0]);
        __syncthreads();
        sh[threadIdx.x] = mx[a]; __syncthreads();
        for (int s = TB / 2; s > 0; s >>= 1) {
            if (threadIdx.x < s) sh[threadIdx.x] = max(sh[threadIdx.x], sh[threadIdx.x + s]);
            __syncthreads();
        }
        if (threadIdx.x == 0) atomicMax(&g_bbox[3 + a], sh[0]);
        __syncthreads();
    }
}

// ---------------- 2: count + (last block) scan ----------------
__global__ void __launch_bounds__(TB)
count_scan_kernel(const float* __restrict__ coord, int npts, int seg, int ncells) {
    float lo[3], cw[3], sc[3];
    loadGridParams(lo, cw, sc);

    for (int i = blockIdx.x * TB + threadIdx.x; i < npts; i += gridDim.x * TB) {
        const int cx = cellIdx(coord[3 * i + 0], lo[0], sc[0]);
        const int cy = cellIdx(coord[3 * i + 1], lo[1], sc[1]);
        const int cz = cellIdx(coord[3 * i + 2], lo[2], sc[2]);
        const int cell = (i / seg) * NC + (cz * G + cy) * G + cx;
        g_cellOf[i] = cell;
        atomicAdd(&g_binCnt[cell], 1);
    }

    // last-block-done: run the prefix scan with hot L2
    __shared__ bool isLast;
    __threadfence();
    __syncthreads();
    if (threadIdx.x == 0)
        isLast = (atomicAdd(&g_ticket, 1) == (int)gridDim.x - 1);
    __syncthreads();
    if (!isLast) return;

    // 2-pass scan over ncells by TB threads (per-thread serial, then
    // shuffle-scan of per-thread totals)
    const int per  = (ncells + TB - 1) / TB;
    const int lane = threadIdx.x & 31;
    const int wrp  = threadIdx.x >> 5;

    int tot = 0;
    for (int q = 0; q < per; q++) {
        const int idx = threadIdx.x * per + q;
        if (idx < ncells) tot += g_binCnt[idx];
    }
    // inclusive warp scan
    int inc = tot;
    #pragma unroll
    for (int off = 1; off < 32; off <<= 1) {
        const int v = __shfl_up_sync(0xffffffffu, inc, off);
        if (lane >= off) inc += v;
    }
    __shared__ int wsum[TB / 32];
    if (lane == 31) wsum[wrp] = inc;
    __syncthreads();
    __shared__ int wpre[TB / 32];
    if (threadIdx.x == 0) {
        int s = 0;
        #pragma unroll
        for (int w = 0; w < TB / 32; w++) { wpre[w] = s; s += wsum[w]; }
    }
    __syncthreads();

    int o = wpre[wrp] + (inc - tot);   // exclusive prefix for this thread
    for (int q = 0; q < per; q++) {
        const int idx = threadIdx.x * per + q;
        if (idx < ncells) {
            g_binOff[idx]  = o;
            g_binFill[idx] = o;
            o += g_binCnt[idx];
        }
    }
}

// ---------------- 3: scatter ----------------
__global__ void __launch_bounds__(TB)
scatter_kernel(const float* __restrict__ coord, int npts) {
    const int i = blockIdx.x * TB + threadIdx.x;
    if (i >= npts) return;
    const int pos = atomicAdd(&g_binFill[g_cellOf[i]], 1);
    const float x = coord[3 * i + 0];
    const float y = coord[3 * i + 1];
    const float z = coord[3 * i + 2];
    g_sortedIdx[pos] = i;
    g_packed[pos] = make_float4(-2.f * x, -2.f * y, -2.f * z,
                                x * x + y * y + z * z);
}

// ---------------- 4: knn + per-point loss ----------------
__global__ void __launch_bounds__(TB)
knn_loss_kernel(const float* __restrict__ pred,
                const float* __restrict__ target,
                int npts, int seg) {
    const int k = blockIdx.x * TB + threadIdx.x;   // binned position
    if (k >= npts) return;

    float lo[3], cw[3], sc[3];
    loadGridParams(lo, cw, sc);

    const int   i    = g_sortedIdx[k];
    const int   cell = g_cellOf[i];
    const int   cellBase = (cell / NC) * NC;
    const int   cl   = cell - cellBase;
    const int   cx   = cl & (G - 1);
    const int   cy   = (cl >> 3) & (G - 1);
    const int   cz   = cl >> 6;

    const float4 pk = g_packed[k];
    const float px = -0.5f * pk.x;
    const float py = -0.5f * pk.y;
    const float pz = -0.5f * pk.z;
    const float sqi = pk.w;

    float D0 = FLT_MAX, D1 = FLT_MAX, D2 = FLT_MAX;
    int   J0 = -1, J1 = -1, J2 = -1;

    for (int R = 1; R <= G; R++) {
        const int zlo = max(cz - R, 0), zhi = min(cz + R, G - 1);
        const int ylo = max(cy - R, 0), yhi = min(cy + R, G - 1);
        const int xlo = max(cx - R, 0), xhi = min(cx + R, G - 1);
        for (int zc = zlo; zc <= zhi; zc++) {
            const int adz = abs(zc - cz);
            for (int yc = ylo; yc <= yhi; yc++) {
                const int ady = abs(yc - cy);
                // cells adjacent in x are contiguous in memory (ordered scan),
                // so each new region is 1 or 2 contiguous spans
                int sBeg[2], sEnd[2], ns = 0;
                if (R == 1 || adz == R || ady == R) {
                    sBeg[0] = xlo; sEnd[0] = xhi; ns = 1;
                } else {
                    if (cx - R >= 0)     { sBeg[ns] = cx - R; sEnd[ns] = cx - R; ns++; }
                    if (cx + R <= G - 1) { sBeg[ns] = cx + R; sEnd[ns] = cx + R; ns++; }
                }
                const int rowBase = cellBase + (zc * G + yc) * G;
                for (int sI = 0; sI < ns; sI++) {
                    const int cFirst = rowBase + sBeg[sI];
                    const int cLast  = rowBase + sEnd[sI];
                    const int off = g_binOff[cFirst];
                    const int end = g_binOff[cLast] + g_binCnt[cLast];
                    for (int t = off; t < end; t++) {
                        const float4 c = g_packed[t];
                        const float e = fmaf(c.x, px, fmaf(c.y, py, fmaf(c.z, pz, c.w)));
                        const float d2 = fmaxf(sqi + e, 0.0f);
                        if (d2 <= D2) {
                            const int j = g_sortedIdx[t];
                            if (j != i && lessDJ(d2, j, D2, J2)) {
                                if (lessDJ(d2, j, D1, J1)) {
                                    D2 = D1; J2 = J1;
                                    if (lessDJ(d2, j, D0, J0)) { D1 = D0; J1 = J0; D0 = d2; J0 = j; }
                                    else                       { D1 = d2; J1 = j; }
                                } else { D2 = d2; J2 = j; }
                            }
                        }
                    }
                }
            }
        }
        if (J2 >= 0) {
            float b = FLT_MAX;
            if (cx - R > 0)     b = fminf(b, px - (lo[0] + (float)(cx - R) * cw[0]));
            if (cx + R < G - 1) b = fminf(b, (lo[0] + (float)(cx + R + 1) * cw[0]) - px);
            if (cy - R > 0)     b = fminf(b, py - (lo[1] + (float)(cy - R) * cw[1]));
            if (cy + R < G - 1) b = fminf(b, (lo[1] + (float)(cy + R + 1) * cw[1]) - py);
            if (cz - R > 0)     b = fminf(b, pz - (lo[2] + (float)(cz - R) * cw[2]));
            if (cz + R < G - 1) b = fminf(b, (lo[2] + (float)(cz + R + 1) * cw[2]) - pz);
            if (b == FLT_MAX || D2 <= b * b) break;
        }
    }

    // ---- per-point cosine loss (original ids) ----
    float fx = pred[3 * i + 0], fy = pred[3 * i + 1], fz = pred[3 * i + 2];
    float inpv = sqrtf(fx * fx + fy * fy + fz * fz + 1e-8f) + 1e-10f;
    float pnx = fx / inpv, pny = fy / inpv, pnz = fz / inpv;

    float tx = target[3 * i + 0], ty = target[3 * i + 1], tz = target[3 * i + 2];

    float acc = 0.0f;
    const int nbr[3] = { J0, J1, J2 };
    #pragma unroll
    for (int q = 0; q < 3; q++) {
        const int gj = nbr[q];
        float qx = pred[3 * gj + 0], qy = pred[3 * gj + 1], qz = pred[3 * gj + 2];
        float inq = sqrtf(qx * qx + qy * qy + qz * qz + 1e-8f) + 1e-10f;
        float sim = fminf(fabsf(dot3(qx / inq, qy / inq, qz / inq,
                                     pnx, pny, pnz)), 1.0f);

        float ux = target[3 * gj + 0], uy = target[3 * gj + 1], uz = target[3 * gj + 2];
        float tsim = fminf(fabsf(dot3(ux, uy, uz, tx, ty, tz)), 1.0f);

        float diff = sim - tsim;
        acc = fmaf(diff, diff, acc);
    }
    g_loss[i] = acc;
}

// ---------------- 5: reduce + state reset ----------------
__global__ void __launch_bounds__(1024)
reduce_reset_kernel(float* __restrict__ out, int npts, int ncells, float invCount) {
    const int tid = threadIdx.x;

    // deterministic fixed-order sum: thread t sums a fixed contiguous slice
    const float4* lp = (const float4*)g_loss;
    const int nf4 = npts / 4;
    const int per = (nf4 + 1023) / 1024;
    float s = 0.0f;
    for (int q = 0; q < per; q++) {
        const int idx = tid * per + q;
        if (idx < nf4) {
            const float4 v = lp[idx];
            s += ((v.x + v.y) + (v.z + v.w));
        }
    }
    // warp reduce + smem tree (fixed order)
    #pragma unroll
    for (int off = 16; off > 0; off >>= 1)
        s += __shfl_down_sync(0xffffffffu, s, off);
    __shared__ float wsum[32];
    if ((tid & 31) == 0) wsum[tid >> 5] = s;
    __syncthreads();
    if (tid < 32) {
        float v = (tid < 32) ? wsum[tid] : 0.0f;
        #pragma unroll
        for (int off = 16; off > 0; off >>= 1)
            v += __shfl_down_sync(0xffffffffu, v, off);
        if (tid == 0) out[0] = v * invCount;
    }

    // reset state for next replay
    for (int cidx = tid; cidx < ncells; cidx += 1024) g_binCnt[cidx] = 0;
    if (tid < 3) { g_bbox[tid] = 0xFFFFFFFFu; g_bbox[3 + tid] = 0u; }
    if (tid == 0) g_ticket = 0;
}

extern "C" void kernel_launch(void* const* d_in, const int* in_sizes, int n_in,
                              void* d_out, int out_size) {
    const float* pred   = (const float*)d_in[0];
    const float* coord  = (const float*)d_in[1];
    const float* target = (const float*)d_in[2];
    const int    nseg   = in_sizes[3];
    const int    npts   = in_sizes[0] / 3;
    const int    seg    = npts / nseg;
    const int    ncells = nseg * NC;

    const int gPts = (npts + TB - 1) / TB;

    bbox_kernel<<<64, TB>>>(coord, npts);
    count_scan_kernel<<<128, TB>>>(coord, npts, seg, ncells);
    scatter_kernel<<<gPts, TB>>>(coord, npts);
    knn_loss_kernel<<<gPts, TB>>>(pred, target, npts, seg);

    const float invCount = 1.0f / ((float)npts * 3.0f);
    reduce_reset_kernel<<<1, 1024>>>((float*)d_out, npts, ncells, invCount);
}

// round 16
// speedup vs baseline: 4.2568x; 1.4193x over previous
#include <cuda_runtime.h>
#include <cuda_bf16.h>
#include <float.h>

// Segmented exact 3-NN cosine-consistency loss via per-segment spatial
// binning. 5-launch pipeline (bbox / count+scan / scatter / knn+loss /
// reduce+reset). KNN uses 4 LANES PER POINT: lanes stride the candidate
// stream (4 independent load chains -> latency/4) and butterfly-merge their
// top-3 lists at each ring boundary with lexicographic (d2, j) compare
// (visit-order independent == jax.lax.top_k lower-index tie-break, so the
// nondeterministic scatter order cannot change results). Ring search
// terminates when merged 3rd-best d2 <= dist^2 to searched-box boundary
// (domain-edge faces = infinity). Reduction is fixed-order deterministic.
// State (bbox/ticket/binCnt) is reset by the tail kernel for graph replay.

#define G       8
#define NC      (G * G * G)
#define MAXPTS  32768
#define MAXCELL 16384
#define TB      256
#define LPP     4

__device__ unsigned g_bbox[6] = {0xFFFFFFFFu, 0xFFFFFFFFu, 0xFFFFFFFFu, 0u, 0u, 0u};
__device__ int      g_ticket  = 0;
__device__ int      g_binCnt[MAXCELL];          // zero-initialized
__device__ int      g_binOff[MAXCELL];
__device__ int      g_binFill[MAXCELL];
__device__ int      g_cellOf[MAXPTS];
__device__ int      g_sortedIdx[MAXPTS];
__device__ int      g_cellSorted[MAXPTS];
__device__ float4   g_packed[MAXPTS];           // binned: (-2x,-2y,-2z,|c|^2)
__device__ float    g_loss[MAXPTS];             // by original id

__device__ __forceinline__ unsigned encf(float f) {
    unsigned u = __float_as_uint(f);
    return (u & 0x80000000u) ? ~u : (u | 0x80000000u);
}
__device__ __forceinline__ float decf(unsigned u) {
    u = (u & 0x80000000u) ? (u ^ 0x80000000u) : ~u;
    return __uint_as_float(u);
}
__device__ __forceinline__ float dot3(float ax, float ay, float az,
                                      float bx, float by, float bz) {
    return fmaf(ax, bx, fmaf(ay, by, az * bz));
}
__device__ __forceinline__ bool lessDJ(float da, int ja, float db, int jb) {
    return (da < db) || (da == db && ja < jb);
}
__device__ __forceinline__ void insDJ(float d, int j,
                                      float& D0, int& J0,
                                      float& D1, int& J1,
                                      float& D2, int& J2) {
    if (lessDJ(d, j, D2, J2)) {
        if (lessDJ(d, j, D1, J1)) {
            D2 = D1; J2 = J1;
            if (lessDJ(d, j, D0, J0)) { D1 = D0; J1 = J0; D0 = d; J0 = j; }
            else                      { D1 = d;  J1 = j; }
        } else { D2 = d; J2 = j; }
    }
}
__device__ __forceinline__ void loadGridParams(float* lo, float* cw, float* sc) {
    #pragma unroll
    for (int a = 0; a < 3; a++) {
        const float l = decf(g_bbox[a]);
        const float h = decf(g_bbox[3 + a]);
        const float span = fmaxf(h - l, 1e-20f);
        lo[a] = l;
        cw[a] = span / (float)G;
        sc[a] = (float)G * (1.0f - 1e-6f) / span;
    }
}
__device__ __forceinline__ int cellIdx(float v, float lo, float sc) {
    int c = (int)((v - lo) * sc);
    return min(G - 1, max(0, c));
}

// ---------------- 1: bbox ----------------
__global__ void __launch_bounds__(TB)
bbox_kernel(const float* __restrict__ coord, int npts) {
    __shared__ unsigned sh[TB];
    unsigned mn[3] = {0xFFFFFFFFu, 0xFFFFFFFFu, 0xFFFFFFFFu};
    unsigned mx[3] = {0u, 0u, 0u};
    for (int i = blockIdx.x * TB + threadIdx.x; i < npts; i += gridDim.x * TB) {
        #pragma unroll
        for (int a = 0; a < 3; a++) {
            const unsigned e = encf(coord[3 * i + a]);
            mn[a] = min(mn[a], e);
            mx[a] = max(mx[a], e);
        }
    }
    #pragma unroll
    for (int a = 0; a < 3; a++) {
        sh[threadIdx.x] = mn[a]; __syncthreads();
        for (int s = TB / 2; s > 0; s >>= 1) {
            if (threadIdx.x < s) sh[threadIdx.x] = min(sh[threadIdx.x], sh[threadIdx.x + s]);
            __syncthreads();
        }
        if (threadIdx.x == 0) atomicMin(&g_bbox[a], sh[0]);
        __syncthreads();
        sh[threadIdx.x] = mx[a]; __syncthreads();
        for (int s = TB / 2; s > 0; s >>= 1) {
            if (threadIdx.x < s) sh[threadIdx.x] = max(sh[threadIdx.x], sh[threadIdx.x + s]);
            __syncthreads();
        }
        if (threadIdx.x == 0) atomicMax(&g_bbox[3 + a], sh[0]);
        __syncthreads();
    }
}

// ---------------- 2: count + (last block) scan ----------------
__global__ void __launch_bounds__(TB)
count_scan_kernel(const float* __restrict__ coord, int npts, int seg, int ncells) {
    float lo[3], cw[3], sc[3];
    loadGridParams(lo, cw, sc);

    for (int i = blockIdx.x * TB + threadIdx.x; i < npts; i += gridDim.x * TB) {
        const int cx = cellIdx(coord[3 * i + 0], lo[0], sc[0]);
        const int cy = cellIdx(coord[3 * i + 1], lo[1], sc[1]);
        const int cz = cellIdx(coord[3 * i + 2], lo[2], sc[2]);
        const int cell = (i / seg) * NC + (cz * G + cy) * G + cx;
        g_cellOf[i] = cell;
        atomicAdd(&g_binCnt[cell], 1);
    }

    __shared__ bool isLast;
    __threadfence();
    __syncthreads();
    if (threadIdx.x == 0)
        isLast = (atomicAdd(&g_ticket, 1) == (int)gridDim.x - 1);
    __syncthreads();
    if (!isLast) return;

    const int per  = (ncells + TB - 1) / TB;
    const int lane = threadIdx.x & 31;
    const int wrp  = threadIdx.x >> 5;

    int tot = 0;
    for (int q = 0; q < per; q++) {
        const int idx = threadIdx.x * per + q;
        if (idx < ncells) tot += g_binCnt[idx];
    }
    int inc = tot;
    #pragma unroll
    for (int off = 1; off < 32; off <<= 1) {
        const int v = __shfl_up_sync(0xffffffffu, inc, off);
        if (lane >= off) inc += v;
    }
    __shared__ int wsum[TB / 32];
    if (lane == 31) wsum[wrp] = inc;
    __syncthreads();
    __shared__ int wpre[TB / 32];
    if (threadIdx.x == 0) {
        int s = 0;
        #pragma unroll
        for (int w = 0; w < TB / 32; w++) { wpre[w] = s; s += wsum[w]; }
    }
    __syncthreads();

    int o = wpre[wrp] + (inc - tot);
    for (int q = 0; q < per; q++) {
        const int idx = threadIdx.x * per + q;
        if (idx < ncells) {
            g_binOff[idx]  = o;
            g_binFill[idx] = o;
            o += g_binCnt[idx];
        }
    }
}

// ---------------- 3: scatter ----------------
__global__ void __launch_bounds__(TB)
scatter_kernel(const float* __restrict__ coord, int npts) {
    const int i = blockIdx.x * TB + threadIdx.x;
    if (i >= npts) return;
    const int cell = g_cellOf[i];
    const int pos  = atomicAdd(&g_binFill[cell], 1);
    const float x = coord[3 * i + 0];
    const float y = coord[3 * i + 1];
    const float z = coord[3 * i + 2];
    g_sortedIdx[pos]  = i;
    g_cellSorted[pos] = cell;
    g_packed[pos] = make_float4(-2.f * x, -2.f * y, -2.f * z,
                                x * x + y * y + z * z);
}

// ---------------- 4: knn + per-point loss (4 lanes per point) ----------------
__global__ void __launch_bounds__(TB)
knn_loss_kernel(const float* __restrict__ pred,
                const float* __restrict__ target,
                int npts) {
    const int gtid = blockIdx.x * TB + threadIdx.x;
    const int k    = gtid / LPP;            // binned position
    const int q    = gtid & (LPP - 1);      // lane within point-group
    if (k >= npts) return;

    const int      lane = threadIdx.x & 31;
    const unsigned gm   = 0xFu << (lane & ~(LPP - 1));   // group shfl mask

    float lo[3], cw[3], sc[3];
    loadGridParams(lo, cw, sc);

    const int cell     = g_cellSorted[k];
    const int i        = g_sortedIdx[k];
    const int cellBase = (cell / NC) * NC;
    const int cl       = cell - cellBase;
    const int cx       = cl & (G - 1);
    const int cy       = (cl >> 3) & (G - 1);
    const int cz       = cl >> 6;

    const float4 pk = g_packed[k];
    const float px = -0.5f * pk.x;
    const float py = -0.5f * pk.y;
    const float pz = -0.5f * pk.z;
    const float sqi = pk.w;

    float D0 = FLT_MAX, D1 = FLT_MAX, D2 = FLT_MAX;
    int   J0 = -1, J1 = -1, J2 = -1;

    for (int R = 1; R <= G; R++) {
        const int zlo = max(cz - R, 0), zhi = min(cz + R, G - 1);
        const int ylo = max(cy - R, 0), yhi = min(cy + R, G - 1);
        const int xlo = max(cx - R, 0), xhi = min(cx + R, G - 1);
        for (int zc = zlo; zc <= zhi; zc++) {
            const int adz = abs(zc - cz);
            for (int yc = ylo; yc <= yhi; yc++) {
                const int ady = abs(yc - cy);
                int sBeg[2], sEnd[2], ns = 0;
                if (R == 1 || adz == R || ady == R) {
                    sBeg[0] = xlo; sEnd[0] = xhi; ns = 1;
                } else {
                    if (cx - R >= 0)     { sBeg[ns] = cx - R; sEnd[ns] = cx - R; ns++; }
                    if (cx + R <= G - 1) { sBeg[ns] = cx + R; sEnd[ns] = cx + R; ns++; }
                }
                const int rowBase = cellBase + (zc * G + yc) * G;
                for (int sI = 0; sI < ns; sI++) {
                    const int off = g_binOff[rowBase + sBeg[sI]];
                    const int end = g_binOff[rowBase + sEnd[sI]]
                                  + g_binCnt[rowBase + sEnd[sI]];
                    // lanes stride the span: 4 independent load chains
                    for (int t = off + q; t < end; t += LPP) {
                        const float4 c = g_packed[t];
                        const float e = fmaf(c.x, px, fmaf(c.y, py, fmaf(c.z, pz, c.w)));
                        const float d2 = fmaxf(sqi + e, 0.0f);
                        if (d2 <= D2) {
                            const int j = g_sortedIdx[t];
                            if (j != i) insDJ(d2, j, D0, J0, D1, J1, D2, J2);
                        }
                    }
                }
            }
        }

        // group butterfly-merge of the four top-3 lists (all lanes converge
        // to the identical union list -> identical termination decision)
        #pragma unroll
        for (int off = 1; off < LPP; off <<= 1) {
            const float b0 = __shfl_xor_sync(gm, D0, off);
            const int   m0 = __shfl_xor_sync(gm, J0, off);
            const float b1 = __shfl_xor_sync(gm, D1, off);
            const int   m1 = __shfl_xor_sync(gm, J1, off);
            const float b2 = __shfl_xor_sync(gm, D2, off);
            const int   m2 = __shfl_xor_sync(gm, J2, off);
            insDJ(b0, m0, D0, J0, D1, J1, D2, J2);
            insDJ(b1, m1, D0, J0, D1, J1, D2, J2);
            insDJ(b2, m2, D0, J0, D1, J1, D2, J2);
        }

        if (J2 >= 0) {
            float b = FLT_MAX;
            if (cx - R > 0)     b = fminf(b, px - (lo[0] + (float)(cx - R) * cw[0]));
            if (cx + R < G - 1) b = fminf(b, (lo[0] + (float)(cx + R + 1) * cw[0]) - px);
            if (cy - R > 0)     b = fminf(b, py - (lo[1] + (float)(cy - R) * cw[1]));
            if (cy + R < G - 1) b = fminf(b, (lo[1] + (float)(cy + R + 1) * cw[1]) - py);
            if (cz - R > 0)     b = fminf(b, pz - (lo[2] + (float)(cz - R) * cw[2]));
            if (cz + R < G - 1) b = fminf(b, (lo[2] + (float)(cz + R + 1) * cw[2]) - pz);
            if (b == FLT_MAX || D2 <= b * b) break;
        }
    }

    // ---- per-point cosine loss: lanes 0..2 each handle one neighbor ----
    float acc = 0.0f;
    if (q < 3) {
        float fx = pred[3 * i + 0], fy = pred[3 * i + 1], fz = pred[3 * i + 2];
        float inpv = sqrtf(fx * fx + fy * fy + fz * fz + 1e-8f) + 1e-10f;
        float pnx = fx / inpv, pny = fy / inpv, pnz = fz / inpv;

        float tx = target[3 * i + 0], ty = target[3 * i + 1], tz = target[3 * i + 2];

        const int gj = (q == 0) ? J0 : (q == 1) ? J1 : J2;
        float qx = pred[3 * gj + 0], qy = pred[3 * gj + 1], qz = pred[3 * gj + 2];
        float inq = sqrtf(qx * qx + qy * qy + qz * qz + 1e-8f) + 1e-10f;
        float sim = fminf(fabsf(dot3(qx / inq, qy / inq, qz / inq,
                                     pnx, pny, pnz)), 1.0f);

        float ux = target[3 * gj + 0], uy = target[3 * gj + 1], uz = target[3 * gj + 2];
        float tsim = fminf(fabsf(dot3(ux, uy, uz, tx, ty, tz)), 1.0f);

        const float diff = sim - tsim;
        acc = diff * diff;
    }
    // group sum (fixed order within group)
    #pragma unroll
    for (int off = 1; off < LPP; off <<= 1)
        acc += __shfl_xor_sync(gm, acc, off);
    if (q == 0) g_loss[i] = acc;
}

// ---------------- 5: reduce + state reset ----------------
__global__ void __launch_bounds__(1024)
reduce_reset_kernel(float* __restrict__ out, int npts, int ncells, float invCount) {
    const int tid = threadIdx.x;

    const float4* lp = (const float4*)g_loss;
    const int nf4 = npts / 4;
    const int per = (nf4 + 1023) / 1024;
    float s = 0.0f;
    for (int q = 0; q < per; q++) {
        const int idx = tid * per + q;
        if (idx < nf4) {
            const float4 v = lp[idx];
            s += ((v.x + v.y) + (v.z + v.w));
        }
    }
    #pragma unroll
    for (int off = 16; off > 0; off >>= 1)
        s += __shfl_down_sync(0xffffffffu, s, off);
    __shared__ float wsum[32];
    if ((tid & 31) == 0) wsum[tid >> 5] = s;
    __syncthreads();
    if (tid < 32) {
        float v = wsum[tid];
        #pragma unroll
        for (int off = 16; off > 0; off >>= 1)
            v += __shfl_down_sync(0xffffffffu, v, off);
        if (tid == 0) out[0] = v * invCount;
    }

    for (int cidx = tid; cidx < ncells; cidx += 1024) g_binCnt[cidx] = 0;
    if (tid < 3) { g_bbox[tid] = 0xFFFFFFFFu; g_bbox[3 + tid] = 0u; }
    if (tid == 0) g_ticket = 0;
}

extern "C" void kernel_launch(void* const* d_in, const int* in_sizes, int n_in,
                              void* d_out, int out_size) {
    const float* pred   = (const float*)d_in[0];
    const float* coord  = (const float*)d_in[1];
    const float* target = (const float*)d_in[2];
    const int    nseg   = in_sizes[3];
    const int    npts   = in_sizes[0] / 3;
    const int    seg    = npts / nseg;
    const int    ncells = nseg * NC;

    const int gPts = (npts + TB - 1) / TB;
    const int gKnn = (npts * LPP + TB - 1) / TB;

    bbox_kernel<<<64, TB>>>(coord, npts);
    count_scan_kernel<<<128, TB>>>(coord, npts, seg, ncells);
    scatter_kernel<<<gPts, TB>>>(coord, npts);
    knn_loss_kernel<<<gKnn, TB>>>(pred, target, npts);

    const float invCount = 1.0f / ((float)npts * 3.0f);
    reduce_reset_kernel<<<1, 1024>>>((float*)d_out, npts, ncells, invCount);
}